// round 7
// baseline (speedup 1.0000x reference)
#include <cuda_runtime.h>
#include <cuda_bf16.h>
#include <cstdint>
#include <math.h>

#define SEQ   2048
#define HD    128
#define NROT  64
#define NROWS (4 * 2048 * 32)     // 262144 rows of 128
#define TILES (NROWS / 128)       // 2048
#define GRID  152
#define NTHREADS 512

// main-kernel SMEM layout (bytes)
#define SMEM_B    0               // 64KB: B fragments (hi then lo), mma frag order
#define SMEM_A    65536           // 2 bufs x 64KB (hi 32KB + lo 32KB each)
#define SMEM_SZ   196608

// ---------------- device globals (allocation-free scratch) ----------------
__device__ uint2  g_Bfrag[2 * 8 * 16 * 32];   // [hl][kt][nt][lane] -> (b0,b1)
__device__ float2 g_SC[SEQ * 64];             // (sin, cos) per (pos, freq)

// ---------------- helpers ----------------
__device__ __forceinline__ uint32_t smem_u32(const void* p) {
    uint32_t a;
    asm("{ .reg .u64 t; cvta.to.shared.u64 t, %1; cvt.u32.u64 %0, t; }" : "=r"(a) : "l"(p));
    return a;
}

#define LDMATRIX_X4(r, addr) \
    asm volatile("ldmatrix.sync.aligned.m8n8.x4.shared.b16 {%0,%1,%2,%3}, [%4];" \
        : "=r"((r)[0]), "=r"((r)[1]), "=r"((r)[2]), "=r"((r)[3]) : "r"(addr))

#define MMA16816(d, a, b0v, b1v) \
    asm volatile("mma.sync.aligned.m16n8k16.row.col.f32.bf16.bf16.f32 " \
        "{%0,%1,%2,%3}, {%4,%5,%6,%7}, {%8,%9}, {%0,%1,%2,%3};" \
        : "+f"((d)[0]), "+f"((d)[1]), "+f"((d)[2]), "+f"((d)[3]) \
        : "r"((a)[0]), "r"((a)[1]), "r"((a)[2]), "r"((a)[3]), "r"(b0v), "r"(b1v))

// ---------------- fused prep kernel ----------------
// blocks 0..63 : fold rotations -> G, compute 2 M columns, pack B fragments
// blocks 64..95: fill the (pos, freq) sin/cos table
__global__ void prep_kernel(const float* __restrict__ thetas,
                            const float* __restrict__ pairs,
                            const float* __restrict__ scale,
                            const float* __restrict__ Rm,
                            const float* __restrict__ inv_freq) {
    const int tid = threadIdx.x;

    if (blockIdx.x >= 64) {
        int base = (blockIdx.x - 64) * 256 + tid;    // 0..8191
        #pragma unroll
        for (int r = 0; r < 16; r++) {
            int e = base + r * 8192;
            int s = e >> 6, d = e & 63;
            float a = (float)s * inv_freq[d];
            float sv, cv;
            sincosf(a, &sv, &cv);
            g_SC[e] = make_float2(sv, cv);
        }
        return;
    }

    extern __shared__ float ps[];
    float (*G)[HD + 1] = (float (*)[HD + 1])ps;                 // [128][129]
    float (*Mc)[2]     = (float (*)[2])(ps + 128 * (HD + 1));   // [128][2]
    float* cs = ps + 128 * (HD + 1) + 256;       // cos[64]
    float* sn = cs + 64;                         // sin[64]
    int*   ij = (int*)(sn + 64);                 // i[64], j[64]

    if (tid < 64) {
        float th = thetas[tid] * scale[0];
        float s, c;
        sincosf(th, &s, &c);
        cs[tid] = c; sn[tid] = s;
        ij[tid]      = (int)pairs[2 * tid];
        ij[64 + tid] = (int)pairs[2 * tid + 1];
    }
    __syncthreads();

    if (tid < 128) {
        const int t = tid;
        #pragma unroll
        for (int c = 0; c < HD; c++) G[t][c] = (t == c) ? 1.f : 0.f;
        for (int k = 0; k < NROT; k++) {
            int   i   = ij[k];
            int   j   = ij[64 + k];
            float cth = cs[k], sth = sn[k];
            float gi = G[t][i], gj = G[t][j];
            if (i == j) { G[t][i] = gi * cth; }
            else { G[t][i] = gi * cth + gj * sth; G[t][j] = -gi * sth + gj * cth; }
        }
    }
    __syncthreads();

    {
        const int k  = tid >> 1;
        const int nl = tid & 1;
        const int n  = blockIdx.x * 2 + nl;
        float acc = 0.f;
        #pragma unroll 8
        for (int j = 0; j < HD; j++) acc += G[k][j] * Rm[j * HD + n];
        Mc[k][nl] = acc;
    }
    __syncthreads();

    if (tid < 128) {
        const int nl  = tid >> 6;
        const int hl  = (tid >> 5) & 1;
        const int kt  = (tid >> 2) & 7;
        const int tq  = tid & 3;
        const int n   = blockIdx.x * 2 + nl;
        const int nt  = n >> 3;
        const int lane = (n & 7) * 4 + tq;
        const int k0  = kt * 16 + tq * 2;
        uint32_t w[4];
        #pragma unroll
        for (int e = 0; e < 4; e++) {
            float v = Mc[k0 + (e >> 1) * 8 + (e & 1)][nl];
            __nv_bfloat16 h = __float2bfloat16(v);
            if (hl) h = __float2bfloat16(v - __bfloat162float(h));
            w[e] = (uint32_t)*(uint16_t*)&h;
        }
        g_Bfrag[((hl * 8 + kt) * 16 + nt) * 32 + lane] =
            make_uint2(w[0] | (w[1] << 16), w[2] | (w[3] << 16));
    }
}

// ---------------- main kernel ----------------
// A tile SMEM layout (hi or lo, 32KB): row-major 256B/row, 16B chunks
// XOR-swizzled:  addr(row,k) = row*256 + (((k>>3) ^ (row&7))<<4) + (k&7)*2

__device__ __forceinline__ void convert_one(float4 v, int g, uint32_t abase) {
    int r = g >> 5;
    int c = g & 31;
    uint32_t h01, h23, l01, l23;
    asm("cvt.rn.bf16x2.f32 %0, %1, %2;" : "=r"(h01) : "f"(v.y), "f"(v.x));
    asm("cvt.rn.bf16x2.f32 %0, %1, %2;" : "=r"(h23) : "f"(v.w), "f"(v.z));
    float hx = __uint_as_float(h01 << 16);
    float hy = __uint_as_float(h01 & 0xFFFF0000u);
    float hz = __uint_as_float(h23 << 16);
    float hw = __uint_as_float(h23 & 0xFFFF0000u);
    float lx = v.x - hx, ly = v.y - hy, lz = v.z - hz, lw = v.w - hw;
    asm("cvt.rn.bf16x2.f32 %0, %1, %2;" : "=r"(l01) : "f"(ly), "f"(lx));
    asm("cvt.rn.bf16x2.f32 %0, %1, %2;" : "=r"(l23) : "f"(lw), "f"(lz));
    uint32_t off = ((uint32_t)r << 8) + (((((uint32_t)c >> 1) ^ (r & 7)) & 15) << 4)
                 + ((c & 1) << 3);
    asm volatile("st.shared.v2.b32 [%0], {%1, %2};" :: "r"(abase + off), "r"(h01), "r"(h23));
    asm volatile("st.shared.v2.b32 [%0], {%1, %2};" :: "r"(abase + 32768 + off), "r"(l01), "r"(l23));
}

__global__ void __launch_bounds__(NTHREADS, 1)
rotary_mma(const float* __restrict__ x, float* __restrict__ out) {
    extern __shared__ char smem[];
    const uint32_t sb = smem_u32(smem);
    const int tid  = threadIdx.x;
    const int bid  = blockIdx.x;
    const int warp = tid >> 5;
    const int lane = tid & 31;
    const int wm   = warp >> 2;          // 0..3 : 32-row strip (= seq-pos slot)
    const int wn   = warp & 3;           // 0..3 : 32-col strip
    const int gq   = lane >> 2;          // 0..7
    const int tq   = lane & 3;           // 0..3

    // load B fragments into SMEM (64KB)
    {
        const float4* src = (const float4*)g_Bfrag;
        float4* dst = (float4*)(smem + SMEM_B);
        #pragma unroll
        for (int i = 0; i < 8; i++) dst[tid + i * NTHREADS] = src[tid + i * NTHREADS];
    }

    const int nt_tiles = (TILES - bid + GRID - 1) / GRID;
    const float4* x4 = (const float4*)x;
    const uint2*  Bf = (const uint2*)(smem + SMEM_B);

    // ldmatrix per-thread address pieces
    const int lr = lane & 15;
    const int lc = lane >> 4;
    const uint32_t sw = lr & 7;
    uint32_t rowoff[2];
    rowoff[0] = (uint32_t)(wm * 32 + lr) << 8;
    rowoff[1] = (uint32_t)(wm * 32 + 16 + lr) << 8;

    // prologue: convert tile 0 into A[0]
    {
        const float4* xs = x4 + (size_t)bid * 4096;
        #pragma unroll
        for (int i = 0; i < 8; i++)
            convert_one(xs[tid + i * NTHREADS], tid + i * NTHREADS, sb + SMEM_A);
    }
    __syncthreads();

    for (int it = 0; it < nt_tiles; it++) {
        const int buf  = it & 1;
        const int tile = bid + it * GRID;
        const uint32_t abase = sb + SMEM_A + (uint32_t)buf * 65536;
        const uint32_t anext = sb + SMEM_A + (uint32_t)(buf ^ 1) * 65536;
        const bool have_next = (it + 1 < nt_tiles);

        // sin/cos for this warp's position + this thread's 4 freq columns
        float2 scv[4];
        {
            int pos = ((tile << 2) + wm) & (SEQ - 1);
            const float2* scp = g_SC + pos * 64 + wn * 16 + tq;
            #pragma unroll
            for (int n = 0; n < 4; n++) scv[n] = scp[n * 4];
        }

        float acc[2][4][4];
        #pragma unroll
        for (int m = 0; m < 2; m++)
            #pragma unroll
            for (int n = 0; n < 4; n++)
                #pragma unroll
                for (int e = 0; e < 4; e++) acc[m][n][e] = 0.f;

        // pipelined next-tile fetch: 8 float4 per thread
        const float4* xs = x4 + (size_t)(tile + GRID) * 4096;
        float4 q0[8];
        if (have_next) {
            #pragma unroll
            for (int c = 0; c < 4; c++) q0[c] = xs[tid + c * NTHREADS];
        }

        #pragma unroll
        for (int kt = 0; kt < 8; kt++) {
            if (have_next && kt < 4)
                q0[kt + 4] = xs[tid + (kt + 4) * NTHREADS];
            uint32_t Ah[2][4], Al[2][4];
            const uint32_t choff = ((((uint32_t)(kt * 2 + lc)) ^ sw) & 15) << 4;
            #pragma unroll
            for (int m = 0; m < 2; m++) {
                uint32_t ad = abase + rowoff[m] + choff;
                LDMATRIX_X4(Ah[m], ad);
                LDMATRIX_X4(Al[m], ad + 32768);
            }
            #pragma unroll
            for (int n = 0; n < 4; n++) {
                const int ntg = wn * 4 + n;
                uint2 bh = Bf[(kt * 16 + ntg) * 32 + lane];
                uint2 bl = Bf[((8 + kt) * 16 + ntg) * 32 + lane];
                #pragma unroll
                for (int m = 0; m < 2; m++) {
                    MMA16816(acc[m][n], Ah[m], bh.x, bh.y);
                    MMA16816(acc[m][n], Ah[m], bl.x, bl.y);
                    MMA16816(acc[m][n], Al[m], bh.x, bh.y);
                }
            }
            if (have_next)
                convert_one(q0[kt], tid + kt * NTHREADS, anext);
        }
        __syncthreads();   // A[buf^1] complete; all A[buf] frag reads done

        // RoPE + direct scattered STG (no staging; wn strips tile each row)
        {
            float* od = out + (size_t)tile * 16384;
            #pragma unroll
            for (int m = 0; m < 2; m++) {
                #pragma unroll
                for (int h = 0; h < 2; h++) {
                    int row = wm * 32 + m * 16 + h * 8 + gq;
                    float* rp = od + row * 128;
                    #pragma unroll
                    for (int n = 0; n < 4; n++) {
                        float e = acc[m][n][h * 2];
                        float o = acc[m][n][h * 2 + 1];
                        float s = scv[n].x, c = scv[n].y;
                        int d = wn * 16 + n * 4 + tq;
                        rp[d]      = e * c - o * s;
                        rp[64 + d] = e * s + o * c;
                    }
                }
            }
        }
        // no sync needed: epilogue touches no SMEM
    }
}

// ---------------- launcher ----------------
extern "C" void kernel_launch(void* const* d_in, const int* in_sizes, int n_in,
                              void* d_out, int out_size) {
    const float* x        = (const float*)d_in[0];
    const float* thetas   = (const float*)d_in[1];
    const float* pairs    = (const float*)d_in[2];
    const float* scale    = (const float*)d_in[3];
    const float* Rm       = (const float*)d_in[4];
    const float* inv_freq = (const float*)d_in[5];
    float*       out      = (float*)d_out;
    (void)in_sizes; (void)n_in; (void)out_size;

    const int prep_smem = (128 * (HD + 1) + 256 + 128 + 128) * 4;
    cudaFuncSetAttribute(prep_kernel, cudaFuncAttributeMaxDynamicSharedMemorySize, prep_smem);
    cudaFuncSetAttribute(rotary_mma, cudaFuncAttributeMaxDynamicSharedMemorySize, SMEM_SZ);

    prep_kernel<<<96, 256, prep_smem>>>(thetas, pairs, scale, Rm, inv_freq);
    rotary_mma<<<GRID, NTHREADS, SMEM_SZ>>>(x, out);
}

// round 8
// speedup vs baseline: 1.0626x; 1.0626x over previous
#include <cuda_runtime.h>
#include <cuda_bf16.h>
#include <cstdint>
#include <math.h>

#define SEQ   2048
#define HD    128
#define NROT  64
#define NROWS (4 * 2048 * 32)     // 262144 rows of 128
#define TILES (NROWS / 128)       // 2048
#define GRID  152
#define NTHREADS 512

// main-kernel SMEM layout (bytes)
#define SMEM_B    0               // 64KB: B fragments (hi then lo), mma frag order
#define SMEM_A    65536           // 2 group bufs x 64KB (hi 32KB + lo 32KB each)
#define SMEM_SZ   196608

// ---------------- device globals (allocation-free scratch) ----------------
__device__ uint2  g_Bfrag[2 * 8 * 16 * 32];   // [hl][kt][nt][lane] -> (b0,b1)
__device__ float2 g_SC[SEQ * 64];             // (sin, cos) per (pos, freq)

// ---------------- helpers ----------------
__device__ __forceinline__ uint32_t smem_u32(const void* p) {
    uint32_t a;
    asm("{ .reg .u64 t; cvta.to.shared.u64 t, %1; cvt.u32.u64 %0, t; }" : "=r"(a) : "l"(p));
    return a;
}

#define LDMATRIX_X4(r, addr) \
    asm volatile("ldmatrix.sync.aligned.m8n8.x4.shared.b16 {%0,%1,%2,%3}, [%4];" \
        : "=r"((r)[0]), "=r"((r)[1]), "=r"((r)[2]), "=r"((r)[3]) : "r"(addr))

#define MMA16816(d, a, b0v, b1v) \
    asm volatile("mma.sync.aligned.m16n8k16.row.col.f32.bf16.bf16.f32 " \
        "{%0,%1,%2,%3}, {%4,%5,%6,%7}, {%8,%9}, {%0,%1,%2,%3};" \
        : "+f"((d)[0]), "+f"((d)[1]), "+f"((d)[2]), "+f"((d)[3]) \
        : "r"((a)[0]), "r"((a)[1]), "r"((a)[2]), "r"((a)[3]), "r"(b0v), "r"(b1v))

#define BAR_GRP(id) asm volatile("bar.sync %0, 256;" :: "r"(id) : "memory")

// ---------------- fused prep kernel ----------------
// blocks 0..63 : fold rotations -> G, compute 2 M columns, pack B fragments
// blocks 64..95: fill the (pos, freq) sin/cos table
__global__ void prep_kernel(const float* __restrict__ thetas,
                            const float* __restrict__ pairs,
                            const float* __restrict__ scale,
                            const float* __restrict__ Rm,
                            const float* __restrict__ inv_freq) {
    const int tid = threadIdx.x;

    if (blockIdx.x >= 64) {
        int base = (blockIdx.x - 64) * 256 + tid;    // 0..8191
        #pragma unroll
        for (int r = 0; r < 16; r++) {
            int e = base + r * 8192;
            int s = e >> 6, d = e & 63;
            float a = (float)s * inv_freq[d];
            float sv, cv;
            sincosf(a, &sv, &cv);
            g_SC[e] = make_float2(sv, cv);
        }
        return;
    }

    extern __shared__ float ps[];
    float (*G)[HD + 1] = (float (*)[HD + 1])ps;                 // [128][129]
    float (*Mc)[2]     = (float (*)[2])(ps + 128 * (HD + 1));   // [128][2]
    float* cs = ps + 128 * (HD + 1) + 256;       // cos[64]
    float* sn = cs + 64;                         // sin[64]
    int*   ij = (int*)(sn + 64);                 // i[64], j[64]

    if (tid < 64) {
        float th = thetas[tid] * scale[0];
        float s, c;
        sincosf(th, &s, &c);
        cs[tid] = c; sn[tid] = s;
        ij[tid]      = (int)pairs[2 * tid];
        ij[64 + tid] = (int)pairs[2 * tid + 1];
    }
    __syncthreads();

    if (tid < 128) {
        const int t = tid;
        #pragma unroll
        for (int c = 0; c < HD; c++) G[t][c] = (t == c) ? 1.f : 0.f;
        for (int k = 0; k < NROT; k++) {
            int   i   = ij[k];
            int   j   = ij[64 + k];
            float cth = cs[k], sth = sn[k];
            float gi = G[t][i], gj = G[t][j];
            if (i == j) { G[t][i] = gi * cth; }
            else { G[t][i] = gi * cth + gj * sth; G[t][j] = -gi * sth + gj * cth; }
        }
    }
    __syncthreads();

    {
        const int k  = tid >> 1;
        const int nl = tid & 1;
        const int n  = blockIdx.x * 2 + nl;
        float acc = 0.f;
        #pragma unroll 8
        for (int j = 0; j < HD; j++) acc += G[k][j] * Rm[j * HD + n];
        Mc[k][nl] = acc;
    }
    __syncthreads();

    if (tid < 128) {
        const int nl  = tid >> 6;
        const int hl  = (tid >> 5) & 1;
        const int kt  = (tid >> 2) & 7;
        const int tq  = tid & 3;
        const int n   = blockIdx.x * 2 + nl;
        const int nt  = n >> 3;
        const int lane = (n & 7) * 4 + tq;
        const int k0  = kt * 16 + tq * 2;
        uint32_t w[4];
        #pragma unroll
        for (int e = 0; e < 4; e++) {
            float v = Mc[k0 + (e >> 1) * 8 + (e & 1)][nl];
            __nv_bfloat16 h = __float2bfloat16(v);
            if (hl) h = __float2bfloat16(v - __bfloat162float(h));
            w[e] = (uint32_t)*(uint16_t*)&h;
        }
        g_Bfrag[((hl * 8 + kt) * 16 + nt) * 32 + lane] =
            make_uint2(w[0] | (w[1] << 16), w[2] | (w[3] << 16));
    }
}

// ---------------- main kernel ----------------
// A tile SMEM layout (hi or lo, 32KB): row-major 256B/row, 16B chunks
// XOR-swizzled:  addr(row,k) = row*256 + (((k>>3) ^ (row&7))<<4) + (k&7)*2

__device__ __forceinline__ void convert_one(float4 v, int g, uint32_t abase) {
    int r = g >> 5;
    int c = g & 31;
    uint32_t h01, h23, l01, l23;
    asm("cvt.rn.bf16x2.f32 %0, %1, %2;" : "=r"(h01) : "f"(v.y), "f"(v.x));
    asm("cvt.rn.bf16x2.f32 %0, %1, %2;" : "=r"(h23) : "f"(v.w), "f"(v.z));
    float hx = __uint_as_float(h01 << 16);
    float hy = __uint_as_float(h01 & 0xFFFF0000u);
    float hz = __uint_as_float(h23 << 16);
    float hw = __uint_as_float(h23 & 0xFFFF0000u);
    float lx = v.x - hx, ly = v.y - hy, lz = v.z - hz, lw = v.w - hw;
    asm("cvt.rn.bf16x2.f32 %0, %1, %2;" : "=r"(l01) : "f"(ly), "f"(lx));
    asm("cvt.rn.bf16x2.f32 %0, %1, %2;" : "=r"(l23) : "f"(lw), "f"(lz));
    uint32_t off = ((uint32_t)r << 8) + (((((uint32_t)c >> 1) ^ (r & 7)) & 15) << 4)
                 + ((c & 1) << 3);
    asm volatile("st.shared.v2.b32 [%0], {%1, %2};" :: "r"(abase + off), "r"(h01), "r"(h23));
    asm volatile("st.shared.v2.b32 [%0], {%1, %2};" :: "r"(abase + 32768 + off), "r"(l01), "r"(l23));
}

__global__ void __launch_bounds__(NTHREADS, 1)
rotary_mma(const float* __restrict__ x, float* __restrict__ out) {
    extern __shared__ char smem[];
    const uint32_t sb = smem_u32(smem);
    const int tid  = threadIdx.x;
    const int bid  = blockIdx.x;
    const int warp = tid >> 5;
    const int lane = tid & 31;
    const int grp  = warp >> 3;          // 0/1 : independent tile group
    const int wg   = warp & 7;           // warp within group
    const int wm   = wg >> 1;            // 0..3 : 32-row strip (= seq-pos slot)
    const int wn   = wg & 1;             // 0..1 : 64-col strip
    const int gq   = lane >> 2;          // 0..7
    const int tq   = lane & 3;           // 0..3
    const int gtid = tid & 255;          // thread id within group

    // load B fragments into SMEM (64KB, all 512 threads)
    {
        const float4* src = (const float4*)g_Bfrag;
        float4* dst = (float4*)(smem + SMEM_B);
        #pragma unroll
        for (int i = 0; i < 8; i++) dst[tid + i * NTHREADS] = src[tid + i * NTHREADS];
    }
    __syncthreads();

    const int nt = (TILES - bid + GRID - 1) / GRID;
    const float4* x4 = (const float4*)x;
    float4*       o4 = (float4*)out;
    const uint2*  Bf = (const uint2*)(smem + SMEM_B);

    const uint32_t abase = sb + SMEM_A + (uint32_t)grp * 65536;
    const int barid = grp + 1;

    // ldmatrix per-thread address pieces
    const int lr = lane & 15;
    const int lc = lane >> 4;
    const uint32_t sw = lr & 7;
    uint32_t rowoff[2];
    rowoff[0] = (uint32_t)(wm * 32 + lr) << 8;
    rowoff[1] = (uint32_t)(wm * 32 + 16 + lr) << 8;

    for (int j = grp; j < nt; j += 2) {
        const int tile = bid + j * GRID;

        // ---- convert phase: x tile -> bf16 hi/lo in A_grp ----
        {
            const float4* xs = x4 + (size_t)tile * 4096;
            #pragma unroll
            for (int i = 0; i < 16; i++)
                convert_one(xs[gtid + i * 256], gtid + i * 256, abase);
        }
        BAR_GRP(barid);

        // ---- MMA phase ----
        float acc[2][8][4];
        #pragma unroll
        for (int m = 0; m < 2; m++)
            #pragma unroll
            for (int n = 0; n < 8; n++)
                #pragma unroll
                for (int e = 0; e < 4; e++) acc[m][n][e] = 0.f;

        #pragma unroll
        for (int kt = 0; kt < 8; kt++) {
            uint32_t Ah[2][4], Al[2][4];
            const uint32_t choff = ((((uint32_t)(kt * 2 + lc)) ^ sw) & 15) << 4;
            #pragma unroll
            for (int m = 0; m < 2; m++) {
                uint32_t ad = abase + rowoff[m] + choff;
                LDMATRIX_X4(Ah[m], ad);
                LDMATRIX_X4(Al[m], ad + 32768);
            }
            #pragma unroll
            for (int n = 0; n < 8; n++) {
                const int ntg = wn * 8 + n;
                uint2 bh = Bf[(kt * 16 + ntg) * 32 + lane];
                uint2 bl = Bf[((8 + kt) * 16 + ntg) * 32 + lane];
                #pragma unroll
                for (int m = 0; m < 2; m++) {
                    MMA16816(acc[m][n], Ah[m], bh.x, bh.y);
                    MMA16816(acc[m][n], Ah[m], bl.x, bl.y);
                    MMA16816(acc[m][n], Al[m], bh.x, bh.y);
                }
            }
        }

        // sin/cos for this warp's position + this thread's 8 freq columns
        float2 scv[8];
        {
            int pos = ((tile << 2) + wm) & (SEQ - 1);
            const float2* scp = g_SC + pos * 64 + wn * 32 + tq;
            #pragma unroll
            for (int n = 0; n < 8; n++) scv[n] = scp[n * 4];
        }
        BAR_GRP(barid);   // all A_grp fragment reads done -> reuse as f32 stage

        // ---- epilogue: RoPE + staged transpose + coalesced STG ----
        {
            float* stage = (float*)(smem + SMEM_A + (size_t)grp * 65536);
            #pragma unroll
            for (int m = 0; m < 2; m++) {
                #pragma unroll
                for (int h = 0; h < 2; h++) {
                    int row = wm * 32 + m * 16 + h * 8 + gq;
                    int sw2 = row & 7;
                    float* rp = stage + row * 128 + tq;
                    #pragma unroll
                    for (int n = 0; n < 8; n++) {
                        float e = acc[m][n][h * 2];
                        float o = acc[m][n][h * 2 + 1];
                        float s = scv[n].x, c = scv[n].y;
                        int c4 = wn * 8 + n;
                        rp[((c4       ^ sw2) << 2)] = e * c - o * s;   // col d
                        rp[(((16 + c4) ^ sw2) << 2)] = e * s + o * c;  // col 64+d
                    }
                }
            }
        }
        BAR_GRP(barid);

        {
            const float* stage = (const float*)(smem + SMEM_A + (size_t)grp * 65536);
            float4* od = o4 + (size_t)tile * 4096;
            #pragma unroll
            for (int i = 0; i < 16; i++) {
                int g = gtid + i * 256;
                int row = g >> 5, c4 = g & 31;
                od[g] = *(const float4*)&stage[row * 128 + ((c4 ^ (row & 7)) << 2)];
            }
        }
        BAR_GRP(barid);   // stage free -> next convert may overwrite
    }
}

// ---------------- launcher ----------------
extern "C" void kernel_launch(void* const* d_in, const int* in_sizes, int n_in,
                              void* d_out, int out_size) {
    const float* x        = (const float*)d_in[0];
    const float* thetas   = (const float*)d_in[1];
    const float* pairs    = (const float*)d_in[2];
    const float* scale    = (const float*)d_in[3];
    const float* Rm       = (const float*)d_in[4];
    const float* inv_freq = (const float*)d_in[5];
    float*       out      = (float*)d_out;
    (void)in_sizes; (void)n_in; (void)out_size;

    const int prep_smem = (128 * (HD + 1) + 256 + 128 + 128) * 4;
    cudaFuncSetAttribute(prep_kernel, cudaFuncAttributeMaxDynamicSharedMemorySize, prep_smem);
    cudaFuncSetAttribute(rotary_mma, cudaFuncAttributeMaxDynamicSharedMemorySize, SMEM_SZ);

    prep_kernel<<<96, 256, prep_smem>>>(thetas, pairs, scale, Rm, inv_freq);
    rotary_mma<<<GRID, NTHREADS, SMEM_SZ>>>(x, out);
}

// round 9
// speedup vs baseline: 1.2964x; 1.2200x over previous
#include <cuda_runtime.h>
#include <cuda_fp16.h>
#include <cstdint>
#include <math.h>

#define SEQ   2048
#define HD    128
#define NROT  64
#define NROWS (4 * 2048 * 32)     // 262144 rows of 128
#define TILES (NROWS / 128)       // 2048
#define GRID  152
#define NTHREADS 512

// main-kernel SMEM layout (bytes)
#define SMEM_B    0               // 64KB: B fragments fp16 hi+lo, LDS.128-friendly
#define SMEM_A    65536           // 2 bufs x 32KB (fp16 x-tile)
#define SMEM_ST   131072          // 64KB f32 epilogue stage
#define SMEM_SZ   196608

// ---------------- device globals (allocation-free scratch) ----------------
// B pack: uint4 [kt][hl][wn][c2][lane]; uint4 = (b0,b1) for ntg=wn*4+c2*2 and ntg+1
__device__ uint4  g_Bp[8 * 2 * 4 * 2 * 32];
__device__ float2 g_SC[SEQ * 64];             // (sin, cos) per (pos, freq)

// ---------------- helpers ----------------
__device__ __forceinline__ uint32_t smem_u32(const void* p) {
    uint32_t a;
    asm("{ .reg .u64 t; cvta.to.shared.u64 t, %1; cvt.u32.u64 %0, t; }" : "=r"(a) : "l"(p));
    return a;
}

#define LDMATRIX_X4(r, addr) \
    asm volatile("ldmatrix.sync.aligned.m8n8.x4.shared.b16 {%0,%1,%2,%3}, [%4];" \
        : "=r"((r)[0]), "=r"((r)[1]), "=r"((r)[2]), "=r"((r)[3]) : "r"(addr))

#define MMA16816(d, a, b0v, b1v) \
    asm volatile("mma.sync.aligned.m16n8k16.row.col.f32.f16.f16.f32 " \
        "{%0,%1,%2,%3}, {%4,%5,%6,%7}, {%8,%9}, {%0,%1,%2,%3};" \
        : "+f"((d)[0]), "+f"((d)[1]), "+f"((d)[2]), "+f"((d)[3]) \
        : "r"((a)[0]), "r"((a)[1]), "r"((a)[2]), "r"((a)[3]), "r"(b0v), "r"(b1v))

// ---------------- fused prep kernel ----------------
// blocks 0..63 : fold rotations -> G, compute 2 M columns, pack B fragments
// blocks 64..95: fill the (pos, freq) sin/cos table
__global__ void prep_kernel(const float* __restrict__ thetas,
                            const float* __restrict__ pairs,
                            const float* __restrict__ scale,
                            const float* __restrict__ Rm,
                            const float* __restrict__ inv_freq) {
    const int tid = threadIdx.x;

    if (blockIdx.x >= 64) {
        int base = (blockIdx.x - 64) * 256 + tid;    // 0..8191
        #pragma unroll
        for (int r = 0; r < 16; r++) {
            int e = base + r * 8192;
            int s = e >> 6, d = e & 63;
            float a = (float)s * inv_freq[d];
            float sv, cv;
            sincosf(a, &sv, &cv);
            g_SC[e] = make_float2(sv, cv);
        }
        return;
    }

    extern __shared__ float ps[];
    float (*G)[HD + 1] = (float (*)[HD + 1])ps;                 // [128][129]
    float (*Mc)[2]     = (float (*)[2])(ps + 128 * (HD + 1));   // [128][2]
    float* cs = ps + 128 * (HD + 1) + 256;       // cos[64]
    float* sn = cs + 64;                         // sin[64]
    int*   ij = (int*)(sn + 64);                 // i[64], j[64]

    if (tid < 64) {
        float th = thetas[tid] * scale[0];
        float s, c;
        sincosf(th, &s, &c);
        cs[tid] = c; sn[tid] = s;
        ij[tid]      = (int)pairs[2 * tid];
        ij[64 + tid] = (int)pairs[2 * tid + 1];
    }
    __syncthreads();

    if (tid < 128) {
        const int t = tid;
        #pragma unroll
        for (int c = 0; c < HD; c++) G[t][c] = (t == c) ? 1.f : 0.f;
        for (int k = 0; k < NROT; k++) {
            int   i   = ij[k];
            int   j   = ij[64 + k];
            float cth = cs[k], sth = sn[k];
            float gi = G[t][i], gj = G[t][j];
            if (i == j) { G[t][i] = gi * cth; }
            else { G[t][i] = gi * cth + gj * sth; G[t][j] = -gi * sth + gj * cth; }
        }
    }
    __syncthreads();

    {
        const int k  = tid >> 1;
        const int nl = tid & 1;
        const int n  = blockIdx.x * 2 + nl;
        float acc = 0.f;
        #pragma unroll 8
        for (int j = 0; j < HD; j++) acc += G[k][j] * Rm[j * HD + n];
        Mc[k][nl] = acc;
    }
    __syncthreads();

    // pack: 128 entries per block (2 n x 2 hl x 8 kt x 4 tq), fp16 hi/lo
    if (tid < 128) {
        const int nl  = tid >> 6;
        const int hl  = (tid >> 5) & 1;
        const int kt  = (tid >> 2) & 7;
        const int tq  = tid & 3;
        const int n   = blockIdx.x * 2 + nl;
        const int ntg = n >> 3;
        const int wn  = ntg >> 2;
        const int c2  = (ntg >> 1) & 1;
        const int half = ntg & 1;
        const int lane = (n & 7) * 4 + tq;
        const int k0  = kt * 16 + tq * 2;
        uint32_t w[4];
        #pragma unroll
        for (int e = 0; e < 4; e++) {
            float v = Mc[k0 + (e >> 1) * 8 + (e & 1)][nl];
            __half h = __float2half_rn(v);
            if (hl) h = __float2half_rn(v - __half2float(h));
            w[e] = (uint32_t)*(uint16_t*)&h;
        }
        uint2* bp2 = (uint2*)g_Bp;
        int idx = (((((kt * 2 + hl) * 4 + wn) * 2 + c2) * 32 + lane)) * 2 + half;
        bp2[idx] = make_uint2(w[0] | (w[1] << 16), w[2] | (w[3] << 16));
    }
}

// ---------------- main kernel ----------------
// A tile SMEM layout (fp16, 32KB): row-major 256B/row, 16B chunks
// XOR-swizzled:  addr(row,k16B-chunk) = row*256 + ((chunk ^ (row&7))<<4) + sub

__device__ __forceinline__ void convert_one(float4 v, int g, uint32_t abase) {
    int r = g >> 5;
    int c = g & 31;
    __half2 p01 = __floats2half2_rn(v.x, v.y);
    __half2 p23 = __floats2half2_rn(v.z, v.w);
    uint32_t h01 = *(uint32_t*)&p01;
    uint32_t h23 = *(uint32_t*)&p23;
    uint32_t off = ((uint32_t)r << 8) + (((((uint32_t)c >> 1) ^ (r & 7)) & 15) << 4)
                 + ((c & 1) << 3);
    asm volatile("st.shared.v2.b32 [%0], {%1, %2};" :: "r"(abase + off), "r"(h01), "r"(h23));
}

__global__ void __launch_bounds__(NTHREADS, 1)
rotary_mma(const float* __restrict__ x, float* __restrict__ out) {
    extern __shared__ char smem[];
    const uint32_t sb = smem_u32(smem);
    const int tid  = threadIdx.x;
    const int bid  = blockIdx.x;
    const int warp = tid >> 5;
    const int lane = tid & 31;
    const int wm   = warp >> 2;          // 0..3 : 32-row strip (= seq-pos slot)
    const int wn   = warp & 3;           // 0..3 : 32-col strip
    const int gq   = lane >> 2;          // 0..7
    const int tq   = lane & 3;           // 0..3

    // load B fragments into SMEM (64KB)
    {
        const float4* src = (const float4*)g_Bp;
        float4* dst = (float4*)(smem + SMEM_B);
        #pragma unroll
        for (int i = 0; i < 8; i++) dst[tid + i * NTHREADS] = src[tid + i * NTHREADS];
    }

    const int nt = (TILES - bid + GRID - 1) / GRID;
    const float4* x4 = (const float4*)x;
    float4*       o4 = (float4*)out;
    const uint4*  Bf = (const uint4*)(smem + SMEM_B);

    // ldmatrix per-thread address pieces
    const int lr = lane & 15;
    const int lc = lane >> 4;
    const uint32_t sw = lr & 7;
    uint32_t rowoff[2];
    rowoff[0] = (uint32_t)(wm * 32 + lr) << 8;
    rowoff[1] = (uint32_t)(wm * 32 + 16 + lr) << 8;

    // prologue: convert tile 0 into A[0]
    {
        const float4* xs = x4 + (size_t)bid * 4096;
        #pragma unroll
        for (int i = 0; i < 8; i++)
            convert_one(xs[tid + i * NTHREADS], tid + i * NTHREADS, sb + SMEM_A);
    }
    __syncthreads();

    for (int it = 0; it < nt; it++) {
        const int buf  = it & 1;
        const int tile = bid + it * GRID;
        const uint32_t abase = sb + SMEM_A + (uint32_t)buf * 32768;
        const uint32_t anext = sb + SMEM_A + (uint32_t)(buf ^ 1) * 32768;
        const bool have_next = (it + 1 < nt);

        // sin/cos for this warp's position + this thread's 4 freq columns
        float2 scv[4];
        {
            int pos = ((tile << 2) + wm) & (SEQ - 1);
            const float2* scp = g_SC + pos * 64 + wn * 16 + tq;
            #pragma unroll
            for (int n = 0; n < 4; n++) scv[n] = scp[n * 4];
        }

        float acc[2][4][4];
        #pragma unroll
        for (int m = 0; m < 2; m++)
            #pragma unroll
            for (int n = 0; n < 4; n++)
                #pragma unroll
                for (int e = 0; e < 4; e++) acc[m][n][e] = 0.f;

        // pipelined next-tile fetch: 8 float4 per thread
        const float4* xs = x4 + (size_t)(tile + GRID) * 4096;
        float4 q0[8];
        if (have_next) {
            #pragma unroll
            for (int c = 0; c < 4; c++) q0[c] = xs[tid + c * NTHREADS];
        }

        #pragma unroll
        for (int kt = 0; kt < 8; kt++) {
            if (have_next && kt < 4)
                q0[kt + 4] = xs[tid + (kt + 4) * NTHREADS];
            uint32_t A2[2][4];
            const uint32_t choff = ((((uint32_t)(kt * 2 + lc)) ^ sw) & 15) << 4;
            #pragma unroll
            for (int m = 0; m < 2; m++)
                LDMATRIX_X4(A2[m], abase + rowoff[m] + choff);
            #pragma unroll
            for (int hl = 0; hl < 2; hl++) {
                #pragma unroll
                for (int c2 = 0; c2 < 2; c2++) {
                    uint4 bq = Bf[((((kt * 2 + hl) * 4 + wn) * 2 + c2) * 32) + lane];
                    #pragma unroll
                    for (int m = 0; m < 2; m++) {
                        MMA16816(acc[m][c2 * 2],     A2[m], bq.x, bq.y);
                        MMA16816(acc[m][c2 * 2 + 1], A2[m], bq.z, bq.w);
                    }
                }
            }
            if (have_next)
                convert_one(q0[kt], tid + kt * NTHREADS, anext);
        }
        __syncthreads();   // A[buf^1] writes done; stage copy-out(it-1) done

        // RoPE + staged transpose (separate 64KB stage)
        {
            float* stage = (float*)(smem + SMEM_ST);
            #pragma unroll
            for (int m = 0; m < 2; m++) {
                #pragma unroll
                for (int h = 0; h < 2; h++) {
                    int row = wm * 32 + m * 16 + h * 8 + gq;
                    int sw2 = row & 7;
                    float* rp = stage + row * 128 + tq;
                    #pragma unroll
                    for (int n = 0; n < 4; n++) {
                        float e = acc[m][n][h * 2];
                        float o = acc[m][n][h * 2 + 1];
                        float s = scv[n].x, c = scv[n].y;
                        int c4 = wn * 4 + n;
                        rp[((c4       ^ sw2) << 2)] = e * c - o * s;   // col d
                        rp[(((16 + c4) ^ sw2) << 2)] = e * s + o * c;  // col 64+d
                    }
                }
            }
        }
        __syncthreads();

        // coalesced copy stage -> out
        {
            const float* stage = (const float*)(smem + SMEM_ST);
            float4* od = o4 + (size_t)tile * 4096;
            #pragma unroll
            for (int i = 0; i < 8; i++) {
                int g = tid + i * NTHREADS;
                int row = g >> 5, c4 = g & 31;
                od[g] = *(const float4*)&stage[row * 128 + ((c4 ^ (row & 7)) << 2)];
            }
        }
        // no sync: next iteration's post-MMA sync orders stage reuse
    }
}

// ---------------- launcher ----------------
extern "C" void kernel_launch(void* const* d_in, const int* in_sizes, int n_in,
                              void* d_out, int out_size) {
    const float* x        = (const float*)d_in[0];
    const float* thetas   = (const float*)d_in[1];
    const float* pairs    = (const float*)d_in[2];
    const float* scale    = (const float*)d_in[3];
    const float* Rm       = (const float*)d_in[4];
    const float* inv_freq = (const float*)d_in[5];
    float*       out      = (float*)d_out;
    (void)in_sizes; (void)n_in; (void)out_size;

    const int prep_smem = (128 * (HD + 1) + 256 + 128 + 128) * 4;
    cudaFuncSetAttribute(prep_kernel, cudaFuncAttributeMaxDynamicSharedMemorySize, prep_smem);
    cudaFuncSetAttribute(rotary_mma, cudaFuncAttributeMaxDynamicSharedMemorySize, SMEM_SZ);

    prep_kernel<<<96, 256, prep_smem>>>(thetas, pairs, scale, Rm, inv_freq);
    rotary_mma<<<GRID, NTHREADS, SMEM_SZ>>>(x, out);
}

// round 10
// speedup vs baseline: 1.6760x; 1.2928x over previous
#include <cuda_runtime.h>
#include <cuda_fp16.h>
#include <cstdint>
#include <math.h>

#define SEQ   2048
#define HD    128
#define NROT  64
#define NROWS (4 * 2048 * 32)     // 262144 rows of 128
#define TILES64 (NROWS / 64)      // 4096 tiles of 64 rows
#define GRID  304                 // 2 CTAs per SM
#define NTHREADS 256

// main-kernel SMEM layout (bytes) — 96KB per CTA
#define SMEM_B    0               // 32KB: B fragments fp16 (single precision)
#define SMEM_A    32768           // 2 bufs x 16KB (fp16 x-tile, 64 rows)
#define SMEM_ST   65536           // 32KB f32 epilogue stage
#define SMEM_SZ   98304

// ---------------- device globals (allocation-free scratch) ----------------
// B pack: uint4 [kt][wn][c2][lane]; uint4 = (b0,b1) for ntg=wn*4+c2*2 and ntg+1
__device__ uint4  g_Bp[8 * 4 * 2 * 32];
__device__ float2 g_SC[SEQ * 64];             // (sin, cos) per (pos, freq)

// ---------------- helpers ----------------
__device__ __forceinline__ uint32_t smem_u32(const void* p) {
    uint32_t a;
    asm("{ .reg .u64 t; cvta.to.shared.u64 t, %1; cvt.u32.u64 %0, t; }" : "=r"(a) : "l"(p));
    return a;
}

#define LDMATRIX_X4(r, addr) \
    asm volatile("ldmatrix.sync.aligned.m8n8.x4.shared.b16 {%0,%1,%2,%3}, [%4];" \
        : "=r"((r)[0]), "=r"((r)[1]), "=r"((r)[2]), "=r"((r)[3]) : "r"(addr))

#define MMA16816(d, a, b0v, b1v) \
    asm volatile("mma.sync.aligned.m16n8k16.row.col.f32.f16.f16.f32 " \
        "{%0,%1,%2,%3}, {%4,%5,%6,%7}, {%8,%9}, {%0,%1,%2,%3};" \
        : "+f"((d)[0]), "+f"((d)[1]), "+f"((d)[2]), "+f"((d)[3]) \
        : "r"((a)[0]), "r"((a)[1]), "r"((a)[2]), "r"((a)[3]), "r"(b0v), "r"(b1v))

// ---------------- fused prep kernel ----------------
// blocks 0..63 : fold rotations -> G, compute 2 M columns, pack B fragments
// blocks 64..95: fill the (pos, freq) sin/cos table
__global__ void prep_kernel(const float* __restrict__ thetas,
                            const float* __restrict__ pairs,
                            const float* __restrict__ scale,
                            const float* __restrict__ Rm,
                            const float* __restrict__ inv_freq) {
    const int tid = threadIdx.x;

    if (blockIdx.x >= 64) {
        int base = (blockIdx.x - 64) * 256 + tid;    // 0..8191
        #pragma unroll
        for (int r = 0; r < 16; r++) {
            int e = base + r * 8192;
            int s = e >> 6, d = e & 63;
            float a = (float)s * inv_freq[d];
            float sv, cv;
            sincosf(a, &sv, &cv);
            g_SC[e] = make_float2(sv, cv);
        }
        return;
    }

    extern __shared__ float ps[];
    float (*G)[HD + 1] = (float (*)[HD + 1])ps;                 // [128][129]
    float (*Mc)[2]     = (float (*)[2])(ps + 128 * (HD + 1));   // [128][2]
    float* cs = ps + 128 * (HD + 1) + 256;       // cos[64]
    float* sn = cs + 64;                         // sin[64]
    int*   ij = (int*)(sn + 64);                 // i[64], j[64]

    if (tid < 64) {
        float th = thetas[tid] * scale[0];
        float s, c;
        sincosf(th, &s, &c);
        cs[tid] = c; sn[tid] = s;
        ij[tid]      = (int)pairs[2 * tid];
        ij[64 + tid] = (int)pairs[2 * tid + 1];
    }
    __syncthreads();

    if (tid < 128) {
        const int t = tid;
        #pragma unroll
        for (int c = 0; c < HD; c++) G[t][c] = (t == c) ? 1.f : 0.f;
        for (int k = 0; k < NROT; k++) {
            int   i   = ij[k];
            int   j   = ij[64 + k];
            float cth = cs[k], sth = sn[k];
            float gi = G[t][i], gj = G[t][j];
            if (i == j) { G[t][i] = gi * cth; }
            else { G[t][i] = gi * cth + gj * sth; G[t][j] = -gi * sth + gj * cth; }
        }
    }
    __syncthreads();

    {
        const int k  = tid >> 1;
        const int nl = tid & 1;
        const int n  = blockIdx.x * 2 + nl;
        float acc = 0.f;
        #pragma unroll 8
        for (int j = 0; j < HD; j++) acc += G[k][j] * Rm[j * HD + n];
        Mc[k][nl] = acc;
    }
    __syncthreads();

    // pack: 64 entries per block (2 n x 8 kt x 4 tq), fp16 single precision
    if (tid < 64) {
        const int nl  = tid >> 5;
        const int kt  = (tid >> 2) & 7;
        const int tq  = tid & 3;
        const int n   = blockIdx.x * 2 + nl;
        const int ntg = n >> 3;
        const int wn  = ntg >> 2;
        const int c2  = (ntg >> 1) & 1;
        const int half = ntg & 1;
        const int lane = (n & 7) * 4 + tq;
        const int k0  = kt * 16 + tq * 2;
        uint32_t w[4];
        #pragma unroll
        for (int e = 0; e < 4; e++) {
            float v = Mc[k0 + (e >> 1) * 8 + (e & 1)][nl];
            __half h = __float2half_rn(v);
            w[e] = (uint32_t)*(uint16_t*)&h;
        }
        uint2* bp2 = (uint2*)g_Bp;
        int idx = ((((kt * 4 + wn) * 2 + c2) * 32 + lane)) * 2 + half;
        bp2[idx] = make_uint2(w[0] | (w[1] << 16), w[2] | (w[3] << 16));
    }
}

// ---------------- main kernel ----------------
// A tile SMEM layout (fp16, 16KB, 64 rows): row-major 256B/row, 16B chunks
// XOR-swizzled per 8-row group.

__device__ __forceinline__ void convert_one(float4 v, int g, uint32_t abase) {
    int r = g >> 5;
    int c = g & 31;
    __half2 p01 = __floats2half2_rn(v.x, v.y);
    __half2 p23 = __floats2half2_rn(v.z, v.w);
    uint32_t h01 = *(uint32_t*)&p01;
    uint32_t h23 = *(uint32_t*)&p23;
    uint32_t off = ((uint32_t)r << 8) + (((((uint32_t)c >> 1) ^ (r & 7)) & 15) << 4)
                 + ((c & 1) << 3);
    asm volatile("st.shared.v2.b32 [%0], {%1, %2};" :: "r"(abase + off), "r"(h01), "r"(h23));
}

__global__ void __launch_bounds__(NTHREADS, 2)
rotary_mma(const float* __restrict__ x, float* __restrict__ out) {
    extern __shared__ char smem[];
    const uint32_t sb = smem_u32(smem);
    const int tid  = threadIdx.x;
    const int bid  = blockIdx.x;
    const int warp = tid >> 5;
    const int lane = tid & 31;
    const int wm   = warp >> 2;          // 0..1 : 32-row strip (= seq-pos slot)
    const int wn   = warp & 3;           // 0..3 : 32-col strip
    const int gq   = lane >> 2;          // 0..7
    const int tq   = lane & 3;           // 0..3

    // load B fragments into SMEM (32KB)
    {
        const float4* src = (const float4*)g_Bp;
        float4* dst = (float4*)(smem + SMEM_B);
        #pragma unroll
        for (int i = 0; i < 8; i++) dst[tid + i * NTHREADS] = src[tid + i * NTHREADS];
    }

    const int nt = (TILES64 - bid + GRID - 1) / GRID;
    const float4* x4 = (const float4*)x;
    float4*       o4 = (float4*)out;
    const uint4*  Bf = (const uint4*)(smem + SMEM_B);

    // ldmatrix per-thread address pieces
    const int lr = lane & 15;
    const int lc = lane >> 4;
    const uint32_t sw = lr & 7;
    uint32_t rowoff[2];
    rowoff[0] = (uint32_t)(wm * 32 + lr) << 8;
    rowoff[1] = (uint32_t)(wm * 32 + 16 + lr) << 8;

    // prologue: convert tile 0 into A[0]
    {
        const float4* xs = x4 + (size_t)bid * 2048;
        #pragma unroll
        for (int i = 0; i < 8; i++)
            convert_one(xs[tid + i * NTHREADS], tid + i * NTHREADS, sb + SMEM_A);
    }
    __syncthreads();

    for (int it = 0; it < nt; it++) {
        const int buf  = it & 1;
        const int tile = bid + it * GRID;
        const uint32_t abase = sb + SMEM_A + (uint32_t)buf * 16384;
        const uint32_t anext = sb + SMEM_A + (uint32_t)(buf ^ 1) * 16384;
        const bool have_next = (it + 1 < nt);

        // sin/cos for this warp's position + this thread's 4 freq columns
        float2 scv[4];
        {
            int pos = ((tile << 1) + wm) & (SEQ - 1);
            const float2* scp = g_SC + pos * 64 + wn * 16 + tq;
            #pragma unroll
            for (int n = 0; n < 4; n++) scv[n] = scp[n * 4];
        }

        float acc[2][4][4];
        #pragma unroll
        for (int m = 0; m < 2; m++)
            #pragma unroll
            for (int n = 0; n < 4; n++)
                #pragma unroll
                for (int e = 0; e < 4; e++) acc[m][n][e] = 0.f;

        // pipelined next-tile fetch: 8 float4 per thread
        const float4* xs = x4 + (size_t)(tile + GRID) * 2048;
        float4 q0[8];
        if (have_next) {
            #pragma unroll
            for (int c = 0; c < 4; c++) q0[c] = xs[tid + c * NTHREADS];
        }

        #pragma unroll
        for (int kt = 0; kt < 8; kt++) {
            if (have_next && kt < 4)
                q0[kt + 4] = xs[tid + (kt + 4) * NTHREADS];
            uint32_t A2[2][4];
            const uint32_t choff = ((((uint32_t)(kt * 2 + lc)) ^ sw) & 15) << 4;
            #pragma unroll
            for (int m = 0; m < 2; m++)
                LDMATRIX_X4(A2[m], abase + rowoff[m] + choff);
            #pragma unroll
            for (int c2 = 0; c2 < 2; c2++) {
                uint4 bq = Bf[(((kt * 4 + wn) * 2 + c2) * 32) + lane];
                #pragma unroll
                for (int m = 0; m < 2; m++) {
                    MMA16816(acc[m][c2 * 2],     A2[m], bq.x, bq.y);
                    MMA16816(acc[m][c2 * 2 + 1], A2[m], bq.z, bq.w);
                }
            }
            if (have_next)
                convert_one(q0[kt], tid + kt * NTHREADS, anext);
        }
        __syncthreads();   // A[buf^1] writes done; stage copy-out(it-1) done

        // RoPE + staged transpose (32KB stage, 64 rows)
        {
            float* stage = (float*)(smem + SMEM_ST);
            #pragma unroll
            for (int m = 0; m < 2; m++) {
                #pragma unroll
                for (int h = 0; h < 2; h++) {
                    int row = wm * 32 + m * 16 + h * 8 + gq;
                    int sw2 = row & 7;
                    float* rp = stage + row * 128 + tq;
                    #pragma unroll
                    for (int n = 0; n < 4; n++) {
                        float e = acc[m][n][h * 2];
                        float o = acc[m][n][h * 2 + 1];
                        float s = scv[n].x, c = scv[n].y;
                        int c4 = wn * 4 + n;
                        rp[((c4       ^ sw2) << 2)] = e * c - o * s;   // col d
                        rp[(((16 + c4) ^ sw2) << 2)] = e * s + o * c;  // col 64+d
                    }
                }
            }
        }
        __syncthreads();

        // coalesced copy stage -> out
        {
            const float* stage = (const float*)(smem + SMEM_ST);
            float4* od = o4 + (size_t)tile * 2048;
            #pragma unroll
            for (int i = 0; i < 8; i++) {
                int g = tid + i * NTHREADS;
                int row = g >> 5, c4 = g & 31;
                od[g] = *(const float4*)&stage[row * 128 + ((c4 ^ (row & 7)) << 2)];
            }
        }
        // no sync: next iteration's post-MMA sync orders stage reuse
    }
}

// ---------------- launcher ----------------
extern "C" void kernel_launch(void* const* d_in, const int* in_sizes, int n_in,
                              void* d_out, int out_size) {
    const float* x        = (const float*)d_in[0];
    const float* thetas   = (const float*)d_in[1];
    const float* pairs    = (const float*)d_in[2];
    const float* scale    = (const float*)d_in[3];
    const float* Rm       = (const float*)d_in[4];
    const float* inv_freq = (const float*)d_in[5];
    float*       out      = (float*)d_out;
    (void)in_sizes; (void)n_in; (void)out_size;

    const int prep_smem = (128 * (HD + 1) + 256 + 128 + 128) * 4;
    cudaFuncSetAttribute(prep_kernel, cudaFuncAttributeMaxDynamicSharedMemorySize, prep_smem);
    cudaFuncSetAttribute(rotary_mma, cudaFuncAttributeMaxDynamicSharedMemorySize, SMEM_SZ);

    prep_kernel<<<96, 256, prep_smem>>>(thetas, pairs, scale, Rm, inv_freq);
    rotary_mma<<<GRID, NTHREADS, SMEM_SZ>>>(x, out);
}